// round 7
// baseline (speedup 1.0000x reference)
#include <cuda_runtime.h>
#include <cuda_fp16.h>
#include <cstdint>

#define NN 100000
#define EMAX 3200000
#define HH 4
#define CC 8
#define HC 32
#define GG 512
#define FIN 128
#define NEG 0.2f

#define SB 1024
#define NBLK ((NN + SB - 1) / SB)   // 98

// ---------------- scratch (static device globals; no allocation) ----------------
__device__ int      d_deg[NN];
__device__ int      d_rowoff[NN + 1];
__device__ int      d_cursor[NN];
__device__ int      d_csrsrc[EMAX];
__device__ int      d_bsum[NBLK];
__device__ int      d_bbase[NBLK];
__device__ __half   d_h16[NN * HC];      // fp16 transformed features, 64B rows
__device__ float    d_als[NN * HH];      // attention logits (src side), float4 rows
__device__ float    d_ald[NN * HH];      // attention logits (dst side), float4 rows
__device__ float    d_xbuf[NN * HC];     // layer activations (elu output), fp32
__device__ unsigned d_asmax[HH];         // flipped-uint global max of al_s per head
__device__ float    d_gsum[GG * HC];
__device__ float    d_gcnt[GG];
__device__ int      d_is64_edge;
__device__ int      d_is64_batch;

// ---------------- helpers ----------------
__device__ __forceinline__ float lrelu(float x) { return fmaxf(x, NEG * x); }

__device__ __forceinline__ unsigned flipf(float f) {
    unsigned u = __float_as_uint(f);
    return (u & 0x80000000u) ? ~u : (u | 0x80000000u);
}
__device__ __forceinline__ float unflipf(unsigned u) {
    return (u & 0x80000000u) ? __uint_as_float(u ^ 0x80000000u) : __uint_as_float(~u);
}

// ---------------- dtype detection ----------------
__global__ void detect_kernel(const unsigned* __restrict__ e, const unsigned* __restrict__ b) {
    int t = threadIdx.x;                       // 256 threads
    int anyE = 0, anyB = 0;
    for (int k = t; k < 1024; k += 256) anyE |= (e[2 * k + 1] != 0u);
    for (int k = 2000 + t; k < 6000; k += 256) anyB |= (b[2 * k + 1] != 0u);
    __shared__ int sE, sB;
    if (t == 0) { sE = 0; sB = 0; }
    __syncthreads();
    if (anyE) atomicOr(&sE, 1);
    if (anyB) atomicOr(&sB, 1);
    __syncthreads();
    if (t == 0) { d_is64_edge = !sE; d_is64_batch = !sB; }
}

// ---------------- CSR build ----------------
__global__ void zero_deg_kernel() {
    int i = blockIdx.x * blockDim.x + threadIdx.x;
    if (i < NN) d_deg[i] = 0;
}

__global__ void count_kernel(const void* __restrict__ eidx, int E) {
    int e = blockIdx.x * blockDim.x + threadIdx.x;
    if (e >= E) return;
    int dst;
    if (d_is64_edge) dst = (int)((const long long*)eidx)[(size_t)E + e];
    else             dst = ((const int*)eidx)[(size_t)E + e];
    atomicAdd(&d_deg[dst], 1);
}

// phase 1: per-block sums of deg
__global__ void scan_part1() {
    __shared__ int red[32];
    int t = threadIdx.x;
    int i = blockIdx.x * SB + t;
    int v = (i < NN) ? d_deg[i] : 0;
    int s = v;
    s += __shfl_xor_sync(0xffffffffu, s, 1);
    s += __shfl_xor_sync(0xffffffffu, s, 2);
    s += __shfl_xor_sync(0xffffffffu, s, 4);
    s += __shfl_xor_sync(0xffffffffu, s, 8);
    s += __shfl_xor_sync(0xffffffffu, s, 16);
    if ((t & 31) == 0) red[t >> 5] = s;
    __syncthreads();
    if (t < 32) {
        int x = red[t];
        x += __shfl_xor_sync(0xffffffffu, x, 1);
        x += __shfl_xor_sync(0xffffffffu, x, 2);
        x += __shfl_xor_sync(0xffffffffu, x, 4);
        x += __shfl_xor_sync(0xffffffffu, x, 8);
        x += __shfl_xor_sync(0xffffffffu, x, 16);
        if (t == 0) d_bsum[blockIdx.x] = x;
    }
}

// phase 2: scan the 98 block sums
__global__ void scan_part2() {
    __shared__ int sh[128];
    int t = threadIdx.x;                       // 128
    int v = (t < NBLK) ? d_bsum[t] : 0;
    sh[t] = v;
    __syncthreads();
    for (int off = 1; off < 128; off <<= 1) {
        int x = (t >= off) ? sh[t - off] : 0;
        __syncthreads();
        sh[t] += x;
        __syncthreads();
    }
    if (t < NBLK) d_bbase[t] = sh[t] - v;      // exclusive base
    if (t == NBLK - 1) d_rowoff[NN] = sh[t];
}

// phase 3: local exclusive scan + base
__global__ void scan_part3() {
    __shared__ int sh[SB];
    int t = threadIdx.x;
    int i = blockIdx.x * SB + t;
    int v = (i < NN) ? d_deg[i] : 0;
    sh[t] = v;
    __syncthreads();
    for (int off = 1; off < SB; off <<= 1) {
        int x = (t >= off) ? sh[t - off] : 0;
        __syncthreads();
        sh[t] += x;
        __syncthreads();
    }
    int off = d_bbase[blockIdx.x] + sh[t] - v;
    if (i < NN) { d_rowoff[i] = off; d_cursor[i] = off; }
}

__global__ void scatter_kernel(const void* __restrict__ eidx, int E) {
    int e = blockIdx.x * blockDim.x + threadIdx.x;
    if (e >= E) return;
    int s, dst;
    if (d_is64_edge) {
        s   = (int)((const long long*)eidx)[e];
        dst = (int)((const long long*)eidx)[(size_t)E + e];
    } else {
        s   = ((const int*)eidx)[e];
        dst = ((const int*)eidx)[(size_t)E + e];
    }
    int pos = atomicAdd(&d_cursor[dst], 1);
    d_csrsrc[pos] = s;
}

// ---------------- per-layer node transform ----------------
__global__ void zero_asmax_kernel() {
    if (threadIdx.x < HH) d_asmax[threadIdx.x] = 0u;
}

// Layer 1: h = x @ W (128 -> 32), plus attention logits + global max(al_s)
__global__ void k1_first_kernel(const float* __restrict__ x, const float* __restrict__ W,
                                const float* __restrict__ as_, const float* __restrict__ ad_) {
    __shared__ float sW[FIN * HC];
    __shared__ unsigned smax[HH];
    int t = threadIdx.x;                       // 256
    for (int i = t; i < FIN * HC; i += 256) sW[i] = W[i];
    if (t < HH) smax[t] = 0u;
    __syncthreads();

    int lane = t & 31, w = t >> 5;
    int n = blockIdx.x * 8 + w;                // grid 12500 exact
    float av_s = as_[lane], av_d = ad_[lane];

    float4 xv = ((const float4*)(x + (size_t)n * FIN))[lane];
    float hc = 0.f;
#pragma unroll
    for (int k = 0; k < FIN; k++) {
        float comp = ((k & 3) == 0) ? xv.x : ((k & 3) == 1) ? xv.y : ((k & 3) == 2) ? xv.z : xv.w;
        float xk = __shfl_sync(0xffffffffu, comp, k >> 2);
        hc = fmaf(xk, sW[k * HC + lane], hc);
    }

    float ps = hc * av_s, pd = hc * av_d;
    ps += __shfl_xor_sync(0xffffffffu, ps, 1);
    ps += __shfl_xor_sync(0xffffffffu, ps, 2);
    ps += __shfl_xor_sync(0xffffffffu, ps, 4);
    pd += __shfl_xor_sync(0xffffffffu, pd, 1);
    pd += __shfl_xor_sync(0xffffffffu, pd, 2);
    pd += __shfl_xor_sync(0xffffffffu, pd, 4);

    d_h16[(size_t)n * HC + lane] = __float2half(hc);
    int head = lane >> 3;
    if ((lane & 7) == 0) {
        d_als[n * HH + head] = ps;
        d_ald[n * HH + head] = pd;
        atomicMax(&smax[head], flipf(ps));
    }
    __syncthreads();
    if (t < HH) atomicMax(&d_asmax[t], smax[t]);
}

// Layers 2-4: h = xbuf @ W (32 -> 32), same epilogue
__global__ void k1_small_kernel(const float* __restrict__ W,
                                const float* __restrict__ as_, const float* __restrict__ ad_) {
    __shared__ float sW[HC * HC];
    __shared__ unsigned smax[HH];
    int t = threadIdx.x;                       // 256
    for (int i = t; i < HC * HC; i += 256) sW[i] = W[i];
    if (t < HH) smax[t] = 0u;
    __syncthreads();

    int lane = t & 31, w = t >> 5;
    int n = blockIdx.x * 8 + w;
    float av_s = as_[lane], av_d = ad_[lane];

    float xi = d_xbuf[(size_t)n * HC + lane];
    float hc = 0.f;
#pragma unroll
    for (int k = 0; k < HC; k++) {
        float xk = __shfl_sync(0xffffffffu, xi, k);
        hc = fmaf(xk, sW[k * HC + lane], hc);
    }

    float ps = hc * av_s, pd = hc * av_d;
    ps += __shfl_xor_sync(0xffffffffu, ps, 1);
    ps += __shfl_xor_sync(0xffffffffu, ps, 2);
    ps += __shfl_xor_sync(0xffffffffu, ps, 4);
    pd += __shfl_xor_sync(0xffffffffu, pd, 1);
    pd += __shfl_xor_sync(0xffffffffu, pd, 2);
    pd += __shfl_xor_sync(0xffffffffu, pd, 4);

    d_h16[(size_t)n * HC + lane] = __float2half(hc);
    int head = lane >> 3;
    if ((lane & 7) == 0) {
        d_als[n * HH + head] = ps;
        d_ald[n * HH + head] = pd;
        atomicMax(&smax[head], flipf(ps));
    }
    __syncthreads();
    if (t < HH) atomicMax(&d_asmax[t], smax[t]);
}

// ---------------- edge aggregation: one warp per dst node, single fused pass ----------------
// Softmax via global upper bound m_h = lrelu(max_n al_s[n,h] + al_d[d,h]) (exact).
// q = lane&7 owns channels 4q..4q+3 (head q>>1); g = lane>>3 = edge slot.
// Per 4 edges: 1 broadcast float4 LDG of als[sj] (8 lanes share address),
// 1 LDG.64 of the fp16 h quad, inline per-lane exp. No smem staging, no syncwarp.
__global__ void edge_kernel(const float* __restrict__ bias) {
    int t = threadIdx.x, lane = t & 31, w = t >> 5;
    int d = blockIdx.x * 8 + w;                // grid 12500 exact
    int q = lane & 7, g = lane >> 3;
    int head = q >> 1;                         // head of this 4-channel group
    const uint2* h2 = (const uint2*)d_h16;     // 8B = 4 fp16 channels
    const float4* als4 = (const float4*)d_als;

    float4 aldv = __ldg((const float4*)&d_ald[d * HH]);
    float aldh = (head == 0) ? aldv.x : (head == 1) ? aldv.y : (head == 2) ? aldv.z : aldv.w;
    float asm_ = unflipf(d_asmax[head]);
    float mh = lrelu(asm_ + aldh);

    // self-loop weight for this lane's head
    float4 alsd = __ldg(&als4[d]);
    float alsh = (head == 0) ? alsd.x : (head == 1) ? alsd.y : (head == 2) ? alsd.z : alsd.w;
    float wselfq = __expf(lrelu(alsh + aldh) - mh);

    float4 acc = make_float4(0.f, 0.f, 0.f, 0.f);
    if (g == 0) {
        uint2 hv = __ldg(&h2[(size_t)d * 8 + q]);
        float2 f0 = __half22float2(*(const __half2*)&hv.x);
        float2 f1 = __half22float2(*(const __half2*)&hv.y);
        acc.x = wselfq * f0.x; acc.y = wselfq * f0.y;
        acc.z = wselfq * f1.x; acc.w = wselfq * f1.y;
    }
    float dnl = 0.f;                           // per-lane denom partial (own head, own g)

    int beg = d_rowoff[d], end = d_rowoff[d + 1];
    for (int base = beg; base < end; base += 32) {
        int idx = base + lane;
        int s = (idx < end) ? __ldg(&d_csrsrc[idx]) : 0;
        int rem = end - base;                  // 1..32 valid edges in this chunk
#pragma unroll
        for (int sub = 0; sub < 8; sub++) {
            int j = sub * 4 + g;
            int sj = __shfl_sync(0xffffffffu, s, j);
            float4 a = __ldg(&als4[sj]);       // broadcast across the 8 lanes of slot g
            uint2 hv = __ldg(&h2[(size_t)sj * 8 + q]);
            float av = (head == 0) ? a.x : (head == 1) ? a.y : (head == 2) ? a.z : a.w;
            float wj = (j < rem) ? __expf(lrelu(av + aldh) - mh) : 0.f;
            dnl += wj;
            float2 f0 = __half22float2(*(const __half2*)&hv.x);
            float2 f1 = __half22float2(*(const __half2*)&hv.y);
            acc.x = fmaf(wj, f0.x, acc.x);
            acc.y = fmaf(wj, f0.y, acc.y);
            acc.z = fmaf(wj, f1.x, acc.z);
            acc.w = fmaf(wj, f1.y, acc.w);
        }
    }

    // reduce accumulators + denom across the 4 edge-slot groups (same q)
    acc.x += __shfl_xor_sync(0xffffffffu, acc.x, 8);
    acc.y += __shfl_xor_sync(0xffffffffu, acc.y, 8);
    acc.z += __shfl_xor_sync(0xffffffffu, acc.z, 8);
    acc.w += __shfl_xor_sync(0xffffffffu, acc.w, 8);
    dnl   += __shfl_xor_sync(0xffffffffu, dnl, 8);
    acc.x += __shfl_xor_sync(0xffffffffu, acc.x, 16);
    acc.y += __shfl_xor_sync(0xffffffffu, acc.y, 16);
    acc.z += __shfl_xor_sync(0xffffffffu, acc.z, 16);
    acc.w += __shfl_xor_sync(0xffffffffu, acc.w, 16);
    dnl   += __shfl_xor_sync(0xffffffffu, dnl, 16);

    if (lane < 8) {                            // g == 0 lanes hold the reduced values
        float inv = 1.0f / (wselfq + dnl);
        float4 bq = __ldg(&((const float4*)bias)[q]);
        float4 o;
        o.x = acc.x * inv + bq.x;
        o.y = acc.y * inv + bq.y;
        o.z = acc.z * inv + bq.z;
        o.w = acc.w * inv + bq.w;
        o.x = (o.x > 0.f) ? o.x : (__expf(o.x) - 1.f);
        o.y = (o.y > 0.f) ? o.y : (__expf(o.y) - 1.f);
        o.z = (o.z > 0.f) ? o.z : (__expf(o.z) - 1.f);
        o.w = (o.w > 0.f) ? o.w : (__expf(o.w) - 1.f);
        ((float4*)d_xbuf)[(size_t)d * 8 + q] = o;
    }
}

// ---------------- pooling + fc ----------------
__global__ void zero_pool_kernel() {
    int i = blockIdx.x * blockDim.x + threadIdx.x;
    if (i < GG * HC) d_gsum[i] = 0.f;
    if (i < GG) d_gcnt[i] = 0.f;
}

__global__ void pool_kernel(const void* __restrict__ batch) {
    int t = threadIdx.x, lane = t & 31;
    int n = blockIdx.x * 8 + (t >> 5);
    if (n >= NN) return;
    int g;
    if (d_is64_batch) g = (int)((const long long*)batch)[n];
    else              g = ((const int*)batch)[n];
    atomicAdd(&d_gsum[g * HC + lane], d_xbuf[(size_t)n * HC + lane]);
    if (lane == 0) atomicAdd(&d_gcnt[g], 1.0f);
}

__global__ void final_kernel(const float* __restrict__ fc_w, const float* __restrict__ fc_b,
                             float* __restrict__ out) {
    int g = blockIdx.x * blockDim.x + threadIdx.x;
    if (g >= GG) return;
    float inv = 1.0f / fmaxf(d_gcnt[g], 1.0f);
    float s = 0.f;
#pragma unroll
    for (int c = 0; c < HC; c++) s = fmaf(d_gsum[g * HC + c] * inv, fc_w[c], s);
    out[g] = s + fc_b[0];
}

// ---------------- launch ----------------
extern "C" void kernel_launch(void* const* d_in, const int* in_sizes, int n_in,
                              void* d_out, int out_size) {
    const float* x     = (const float*)d_in[0];
    const void*  eidx  = d_in[1];
    const void*  batch = d_in[2];
    const float* W1  = (const float*)d_in[3];
    const float* as1 = (const float*)d_in[4];
    const float* ad1 = (const float*)d_in[5];
    const float* b1  = (const float*)d_in[6];
    const float* fc_w = (const float*)d_in[19];
    const float* fc_b = (const float*)d_in[20];
    float* out = (float*)d_out;

    int E = in_sizes[1] / 2;
    if (E > EMAX) E = EMAX;
    if (E < 0) E = 0;

    const int NB = NN / 8;                 // 12500 blocks of 8 warps
    const int EB = (E + 255) / 256;

    detect_kernel<<<1, 256>>>((const unsigned*)eidx, (const unsigned*)batch);

    // CSR build (parallel 3-phase scan)
    zero_deg_kernel<<<(NN + 255) / 256, 256>>>();
    if (EB > 0) count_kernel<<<EB, 256>>>(eidx, E);
    scan_part1<<<NBLK, SB>>>();
    scan_part2<<<1, 128>>>();
    scan_part3<<<NBLK, SB>>>();
    if (EB > 0) scatter_kernel<<<EB, 256>>>(eidx, E);

    // Layer 1 (input dim 128)
    zero_asmax_kernel<<<1, 32>>>();
    k1_first_kernel<<<NB, 256>>>(x, W1, as1, ad1);
    edge_kernel<<<NB, 256>>>(b1);

    // Layers 2-4 (input dim 32)
    for (int L = 1; L < 4; L++) {
        const float* W   = (const float*)d_in[3 + 4 * L];
        const float* as_ = (const float*)d_in[4 + 4 * L];
        const float* ad_ = (const float*)d_in[5 + 4 * L];
        const float* b_  = (const float*)d_in[6 + 4 * L];
        zero_asmax_kernel<<<1, 32>>>();
        k1_small_kernel<<<NB, 256>>>(W, as_, ad_);
        edge_kernel<<<NB, 256>>>(b_);
    }

    // Global mean pool + FC
    zero_pool_kernel<<<(GG * HC + 255) / 256, 256>>>();
    pool_kernel<<<NB, 256>>>(batch);
    final_kernel<<<2, 256>>>(fc_w, fc_b, out);
}

// round 9
// speedup vs baseline: 1.0523x; 1.0523x over previous
#include <cuda_runtime.h>
#include <cuda_fp16.h>
#include <cstdint>

#define NN 100000
#define EMAX 3200000
#define HH 4
#define CC 8
#define HC 32
#define GG 512
#define FIN 128
#define NEG 0.2f

#define SB 1024
#define NBLK ((NN + SB - 1) / SB)   // 98

// ---------------- scratch (static device globals; no allocation) ----------------
__device__ int      d_deg[NN];
__device__ int      d_rowoff[NN + 1];
__device__ int      d_cursor[NN];
__device__ int      d_csrsrc[EMAX];
__device__ int      d_bsum[NBLK];
__device__ int      d_bbase[NBLK];
__device__ __half   d_h16[NN * HC];      // fp16 transformed features, 64B rows
__device__ float    d_als[NN * HH];      // attention logits (src side), float4 rows
__device__ float    d_ald[NN * HH];      // attention logits (dst side), float4 rows
__device__ float    d_xbuf[NN * HC];     // layer activations (elu output), fp32
__device__ unsigned d_asmax[HH];         // flipped-uint global max of al_s per head
__device__ float    d_gsum[GG * HC];
__device__ float    d_gcnt[GG];
__device__ int      d_is64_edge;
__device__ int      d_is64_batch;

// ---------------- helpers ----------------
__device__ __forceinline__ float lrelu(float x) { return fmaxf(x, NEG * x); }

__device__ __forceinline__ unsigned flipf(float f) {
    unsigned u = __float_as_uint(f);
    return (u & 0x80000000u) ? ~u : (u | 0x80000000u);
}
__device__ __forceinline__ float unflipf(unsigned u) {
    return (u & 0x80000000u) ? __uint_as_float(u ^ 0x80000000u) : __uint_as_float(~u);
}

// ---------------- dtype detection ----------------
__global__ void detect_kernel(const unsigned* __restrict__ e, const unsigned* __restrict__ b) {
    int t = threadIdx.x;                       // 256 threads
    int anyE = 0, anyB = 0;
    for (int k = t; k < 1024; k += 256) anyE |= (e[2 * k + 1] != 0u);
    for (int k = 2000 + t; k < 6000; k += 256) anyB |= (b[2 * k + 1] != 0u);
    __shared__ int sE, sB;
    if (t == 0) { sE = 0; sB = 0; }
    __syncthreads();
    if (anyE) atomicOr(&sE, 1);
    if (anyB) atomicOr(&sB, 1);
    __syncthreads();
    if (t == 0) { d_is64_edge = !sE; d_is64_batch = !sB; }
}

// ---------------- CSR build ----------------
__global__ void zero_deg_kernel() {
    int i = blockIdx.x * blockDim.x + threadIdx.x;
    if (i < NN) d_deg[i] = 0;
}

__global__ void count_kernel(const void* __restrict__ eidx, int E) {
    int e = blockIdx.x * blockDim.x + threadIdx.x;
    if (e >= E) return;
    int dst;
    if (d_is64_edge) dst = (int)((const long long*)eidx)[(size_t)E + e];
    else             dst = ((const int*)eidx)[(size_t)E + e];
    atomicAdd(&d_deg[dst], 1);
}

// phase 1: per-block sums of deg
__global__ void scan_part1() {
    __shared__ int red[32];
    int t = threadIdx.x;
    int i = blockIdx.x * SB + t;
    int v = (i < NN) ? d_deg[i] : 0;
    int s = v;
    s += __shfl_xor_sync(0xffffffffu, s, 1);
    s += __shfl_xor_sync(0xffffffffu, s, 2);
    s += __shfl_xor_sync(0xffffffffu, s, 4);
    s += __shfl_xor_sync(0xffffffffu, s, 8);
    s += __shfl_xor_sync(0xffffffffu, s, 16);
    if ((t & 31) == 0) red[t >> 5] = s;
    __syncthreads();
    if (t < 32) {
        int x = red[t];
        x += __shfl_xor_sync(0xffffffffu, x, 1);
        x += __shfl_xor_sync(0xffffffffu, x, 2);
        x += __shfl_xor_sync(0xffffffffu, x, 4);
        x += __shfl_xor_sync(0xffffffffu, x, 8);
        x += __shfl_xor_sync(0xffffffffu, x, 16);
        if (t == 0) d_bsum[blockIdx.x] = x;
    }
}

// phase 2: scan the 98 block sums
__global__ void scan_part2() {
    __shared__ int sh[128];
    int t = threadIdx.x;                       // 128
    int v = (t < NBLK) ? d_bsum[t] : 0;
    sh[t] = v;
    __syncthreads();
    for (int off = 1; off < 128; off <<= 1) {
        int x = (t >= off) ? sh[t - off] : 0;
        __syncthreads();
        sh[t] += x;
        __syncthreads();
    }
    if (t < NBLK) d_bbase[t] = sh[t] - v;      // exclusive base
    if (t == NBLK - 1) d_rowoff[NN] = sh[t];
}

// phase 3: local exclusive scan + base
__global__ void scan_part3() {
    __shared__ int sh[SB];
    int t = threadIdx.x;
    int i = blockIdx.x * SB + t;
    int v = (i < NN) ? d_deg[i] : 0;
    sh[t] = v;
    __syncthreads();
    for (int off = 1; off < SB; off <<= 1) {
        int x = (t >= off) ? sh[t - off] : 0;
        __syncthreads();
        sh[t] += x;
        __syncthreads();
    }
    int off = d_bbase[blockIdx.x] + sh[t] - v;
    if (i < NN) { d_rowoff[i] = off; d_cursor[i] = off; }
}

__global__ void scatter_kernel(const void* __restrict__ eidx, int E) {
    int e = blockIdx.x * blockDim.x + threadIdx.x;
    if (e >= E) return;
    int s, dst;
    if (d_is64_edge) {
        s   = (int)((const long long*)eidx)[e];
        dst = (int)((const long long*)eidx)[(size_t)E + e];
    } else {
        s   = ((const int*)eidx)[e];
        dst = ((const int*)eidx)[(size_t)E + e];
    }
    int pos = atomicAdd(&d_cursor[dst], 1);
    d_csrsrc[pos] = s;
}

// ---------------- per-layer node transform ----------------
__global__ void zero_asmax_kernel() {
    if (threadIdx.x < HH) d_asmax[threadIdx.x] = 0u;
}

// Layer 1: h = x @ W (128 -> 32), plus attention logits + global max(al_s)
__global__ void k1_first_kernel(const float* __restrict__ x, const float* __restrict__ W,
                                const float* __restrict__ as_, const float* __restrict__ ad_) {
    __shared__ float sW[FIN * HC];
    __shared__ unsigned smax[HH];
    int t = threadIdx.x;                       // 256
    for (int i = t; i < FIN * HC; i += 256) sW[i] = W[i];
    if (t < HH) smax[t] = 0u;
    __syncthreads();

    int lane = t & 31, w = t >> 5;
    int n = blockIdx.x * 8 + w;                // grid 12500 exact
    float av_s = as_[lane], av_d = ad_[lane];

    float4 xv = ((const float4*)(x + (size_t)n * FIN))[lane];
    float hc = 0.f;
#pragma unroll
    for (int k = 0; k < FIN; k++) {
        float comp = ((k & 3) == 0) ? xv.x : ((k & 3) == 1) ? xv.y : ((k & 3) == 2) ? xv.z : xv.w;
        float xk = __shfl_sync(0xffffffffu, comp, k >> 2);
        hc = fmaf(xk, sW[k * HC + lane], hc);
    }

    float ps = hc * av_s, pd = hc * av_d;
    ps += __shfl_xor_sync(0xffffffffu, ps, 1);
    ps += __shfl_xor_sync(0xffffffffu, ps, 2);
    ps += __shfl_xor_sync(0xffffffffu, ps, 4);
    pd += __shfl_xor_sync(0xffffffffu, pd, 1);
    pd += __shfl_xor_sync(0xffffffffu, pd, 2);
    pd += __shfl_xor_sync(0xffffffffu, pd, 4);

    d_h16[(size_t)n * HC + lane] = __float2half(hc);
    int head = lane >> 3;
    if ((lane & 7) == 0) {
        d_als[n * HH + head] = ps;
        d_ald[n * HH + head] = pd;
        atomicMax(&smax[head], flipf(ps));
    }
    __syncthreads();
    if (t < HH) atomicMax(&d_asmax[t], smax[t]);
}

// Layers 2-4: h = xbuf @ W (32 -> 32), same epilogue
__global__ void k1_small_kernel(const float* __restrict__ W,
                                const float* __restrict__ as_, const float* __restrict__ ad_) {
    __shared__ float sW[HC * HC];
    __shared__ unsigned smax[HH];
    int t = threadIdx.x;                       // 256
    for (int i = t; i < HC * HC; i += 256) sW[i] = W[i];
    if (t < HH) smax[t] = 0u;
    __syncthreads();

    int lane = t & 31, w = t >> 5;
    int n = blockIdx.x * 8 + w;
    float av_s = as_[lane], av_d = ad_[lane];

    float xi = d_xbuf[(size_t)n * HC + lane];
    float hc = 0.f;
#pragma unroll
    for (int k = 0; k < HC; k++) {
        float xk = __shfl_sync(0xffffffffu, xi, k);
        hc = fmaf(xk, sW[k * HC + lane], hc);
    }

    float ps = hc * av_s, pd = hc * av_d;
    ps += __shfl_xor_sync(0xffffffffu, ps, 1);
    ps += __shfl_xor_sync(0xffffffffu, ps, 2);
    ps += __shfl_xor_sync(0xffffffffu, ps, 4);
    pd += __shfl_xor_sync(0xffffffffu, pd, 1);
    pd += __shfl_xor_sync(0xffffffffu, pd, 2);
    pd += __shfl_xor_sync(0xffffffffu, pd, 4);

    d_h16[(size_t)n * HC + lane] = __float2half(hc);
    int head = lane >> 3;
    if ((lane & 7) == 0) {
        d_als[n * HH + head] = ps;
        d_ald[n * HH + head] = pd;
        atomicMax(&smax[head], flipf(ps));
    }
    __syncthreads();
    if (t < HH) atomicMax(&d_asmax[t], smax[t]);
}

// ---------------- edge aggregation: one warp per dst node, two-phase + pipelined ----------------
// Softmax via global upper bound m_h = lrelu(max_n al_s[n,h] + al_d[d,h]) (exact).
// R6 structure (batched phase-A weights -> smem, tight phase-B gather+FMA), plus:
//  - next chunk's csrsrc+als prefetched during phase B (hides 2-chained L2 loads)
//  - phase B stops at nsub = ceil(rem/4) (tail trim)
__global__ void edge_kernel(const float* __restrict__ bias) {
    __shared__ float4 sw[8][32];               // per-warp edge weights [j] = (w0..w3)
    int t = threadIdx.x, lane = t & 31, w = t >> 5;
    int d = blockIdx.x * 8 + w;                // grid 12500 exact
    int q = lane & 7, g = lane >> 3;
    int head = q >> 1;                         // head of this 4-channel group
    float4* swp = sw[w];
    const uint2* h2 = (const uint2*)d_h16;     // 8B = 4 fp16 channels
    const float4* als4 = (const float4*)d_als;

    float4 aldv = __ldg((const float4*)&d_ald[d * HH]);
    float m0 = lrelu(unflipf(d_asmax[0]) + aldv.x);
    float m1 = lrelu(unflipf(d_asmax[1]) + aldv.y);
    float m2 = lrelu(unflipf(d_asmax[2]) + aldv.z);
    float m3 = lrelu(unflipf(d_asmax[3]) + aldv.w);

    // self-loop weight per head
    float4 alsd = __ldg(&als4[d]);
    float s0 = __expf(lrelu(alsd.x + aldv.x) - m0);
    float s1 = __expf(lrelu(alsd.y + aldv.y) - m1);
    float s2 = __expf(lrelu(alsd.z + aldv.z) - m2);
    float s3 = __expf(lrelu(alsd.w + aldv.w) - m3);
    float wselfq = (head == 0) ? s0 : (head == 1) ? s1 : (head == 2) ? s2 : s3;

    float4 acc = make_float4(0.f, 0.f, 0.f, 0.f);
    if (g == 0) {
        uint2 hv = __ldg(&h2[(size_t)d * 8 + q]);
        float2 f0 = __half22float2(*(const __half2*)&hv.x);
        float2 f1 = __half22float2(*(const __half2*)&hv.y);
        acc.x = wselfq * f0.x; acc.y = wselfq * f0.y;
        acc.z = wselfq * f1.x; acc.w = wselfq * f1.y;
    }
    float dn0 = 0.f, dn1 = 0.f, dn2 = 0.f, dn3 = 0.f;

    int beg = d_rowoff[d], end = d_rowoff[d + 1];

    // prefetch first chunk (csrsrc -> als chain)
    int idx0 = beg + lane;
    int s = (idx0 < end) ? __ldg(&d_csrsrc[idx0]) : 0;
    float4 a = __ldg(&als4[s]);

    for (int base = beg; base < end; base += 32) {
        int rem = end - base;                  // 1..inf; valid lanes: lane < rem
        // phase A: compute all 4 head weights from prefetched (s, a)
        float w0 = __expf(lrelu(a.x + aldv.x) - m0);
        float w1 = __expf(lrelu(a.y + aldv.y) - m1);
        float w2 = __expf(lrelu(a.z + aldv.z) - m2);
        float w3 = __expf(lrelu(a.w + aldv.w) - m3);
        if (lane >= rem) { w0 = w1 = w2 = w3 = 0.f; }
        dn0 += w0; dn1 += w1; dn2 += w2; dn3 += w3;
        swp[lane] = make_float4(w0, w1, w2, w3);

        // prefetch next chunk while phase B runs
        int nb = base + 32;
        int nidx = nb + lane;
        int ns = (nidx < end) ? __ldg(&d_csrsrc[nidx]) : 0;
        float4 na = __ldg(&als4[ns]);
        __syncwarp();

        // phase B: 4 edges per iteration; lane handles 4-channel group q of edge sub*4+g
        int nsub = (rem >= 32) ? 8 : ((rem + 3) >> 2);
#pragma unroll 8
        for (int sub = 0; sub < nsub; sub++) {
            int j = sub * 4 + g;
            int sj = __shfl_sync(0xffffffffu, s, j);
            uint2 hv = __ldg(&h2[(size_t)sj * 8 + q]);
            float wj = ((const float*)swp)[j * 4 + head];
            float2 f0 = __half22float2(*(const __half2*)&hv.x);
            float2 f1 = __half22float2(*(const __half2*)&hv.y);
            acc.x = fmaf(wj, f0.x, acc.x);
            acc.y = fmaf(wj, f0.y, acc.y);
            acc.z = fmaf(wj, f1.x, acc.z);
            acc.w = fmaf(wj, f1.y, acc.w);
        }
        __syncwarp();
        s = ns; a = na;
    }

    // reduce accumulators across the 4 edge-slot groups (same q)
    acc.x += __shfl_xor_sync(0xffffffffu, acc.x, 8);
    acc.y += __shfl_xor_sync(0xffffffffu, acc.y, 8);
    acc.z += __shfl_xor_sync(0xffffffffu, acc.z, 8);
    acc.w += __shfl_xor_sync(0xffffffffu, acc.w, 8);
    acc.x += __shfl_xor_sync(0xffffffffu, acc.x, 16);
    acc.y += __shfl_xor_sync(0xffffffffu, acc.y, 16);
    acc.z += __shfl_xor_sync(0xffffffffu, acc.z, 16);
    acc.w += __shfl_xor_sync(0xffffffffu, acc.w, 16);

    // reduce per-head denominators across all lanes
#pragma unroll
    for (int off = 1; off < 32; off <<= 1) {
        dn0 += __shfl_xor_sync(0xffffffffu, dn0, off);
        dn1 += __shfl_xor_sync(0xffffffffu, dn1, off);
        dn2 += __shfl_xor_sync(0xffffffffu, dn2, off);
        dn3 += __shfl_xor_sync(0xffffffffu, dn3, off);
    }

    if (lane < 8) {
        float dh = (head == 0) ? dn0 : (head == 1) ? dn1 : (head == 2) ? dn2 : dn3;
        float inv = 1.0f / (wselfq + dh);
        float4 bq = __ldg(&((const float4*)bias)[q]);
        float4 o;
        o.x = acc.x * inv + bq.x;
        o.y = acc.y * inv + bq.y;
        o.z = acc.z * inv + bq.z;
        o.w = acc.w * inv + bq.w;
        o.x = (o.x > 0.f) ? o.x : (__expf(o.x) - 1.f);
        o.y = (o.y > 0.f) ? o.y : (__expf(o.y) - 1.f);
        o.z = (o.z > 0.f) ? o.z : (__expf(o.z) - 1.f);
        o.w = (o.w > 0.f) ? o.w : (__expf(o.w) - 1.f);
        ((float4*)d_xbuf)[(size_t)d * 8 + q] = o;
    }
}

// ---------------- pooling + fc ----------------
__global__ void zero_pool_kernel() {
    int i = blockIdx.x * blockDim.x + threadIdx.x;
    if (i < GG * HC) d_gsum[i] = 0.f;
    if (i < GG) d_gcnt[i] = 0.f;
}

__global__ void pool_kernel(const void* __restrict__ batch) {
    int t = threadIdx.x, lane = t & 31;
    int n = blockIdx.x * 8 + (t >> 5);
    if (n >= NN) return;
    int g;
    if (d_is64_batch) g = (int)((const long long*)batch)[n];
    else              g = ((const int*)batch)[n];
    atomicAdd(&d_gsum[g * HC + lane], d_xbuf[(size_t)n * HC + lane]);
    if (lane == 0) atomicAdd(&d_gcnt[g], 1.0f);
}

__global__ void final_kernel(const float* __restrict__ fc_w, const float* __restrict__ fc_b,
                             float* __restrict__ out) {
    int g = blockIdx.x * blockDim.x + threadIdx.x;
    if (g >= GG) return;
    float inv = 1.0f / fmaxf(d_gcnt[g], 1.0f);
    float s = 0.f;
#pragma unroll
    for (int c = 0; c < HC; c++) s = fmaf(d_gsum[g * HC + c] * inv, fc_w[c], s);
    out[g] = s + fc_b[0];
}

// ---------------- launch ----------------
extern "C" void kernel_launch(void* const* d_in, const int* in_sizes, int n_in,
                              void* d_out, int out_size) {
    const float* x     = (const float*)d_in[0];
    const void*  eidx  = d_in[1];
    const void*  batch = d_in[2];
    const float* W1  = (const float*)d_in[3];
    const float* as1 = (const float*)d_in[4];
    const float* ad1 = (const float*)d_in[5];
    const float* b1  = (const float*)d_in[6];
    const float* fc_w = (const float*)d_in[19];
    const float* fc_b = (const float*)d_in[20];
    float* out = (float*)d_out;

    int E = in_sizes[1] / 2;
    if (E > EMAX) E = EMAX;
    if (E < 0) E = 0;

    const int NB = NN / 8;                 // 12500 blocks of 8 warps
    const int EB = (E + 255) / 256;

    detect_kernel<<<1, 256>>>((const unsigned*)eidx, (const unsigned*)batch);

    // CSR build (parallel 3-phase scan)
    zero_deg_kernel<<<(NN + 255) / 256, 256>>>();
    if (EB > 0) count_kernel<<<EB, 256>>>(eidx, E);
    scan_part1<<<NBLK, SB>>>();
    scan_part2<<<1, 128>>>();
    scan_part3<<<NBLK, SB>>>();
    if (EB > 0) scatter_kernel<<<EB, 256>>>(eidx, E);

    // Layer 1 (input dim 128)
    zero_asmax_kernel<<<1, 32>>>();
    k1_first_kernel<<<NB, 256>>>(x, W1, as1, ad1);
    edge_kernel<<<NB, 256>>>(b1);

    // Layers 2-4 (input dim 32)
    for (int L = 1; L < 4; L++) {
        const float* W   = (const float*)d_in[3 + 4 * L];
        const float* as_ = (const float*)d_in[4 + 4 * L];
        const float* ad_ = (const float*)d_in[5 + 4 * L];
        const float* b_  = (const float*)d_in[6 + 4 * L];
        zero_asmax_kernel<<<1, 32>>>();
        k1_small_kernel<<<NB, 256>>>(W, as_, ad_);
        edge_kernel<<<NB, 256>>>(b_);
    }

    // Global mean pool + FC
    zero_pool_kernel<<<(GG * HC + 255) / 256, 256>>>();
    pool_kernel<<<NB, 256>>>(batch);
    final_kernel<<<2, 256>>>(fc_w, fc_b, out);
}

// round 10
// speedup vs baseline: 1.1371x; 1.0805x over previous
#include <cuda_runtime.h>
#include <cuda_fp16.h>
#include <cstdint>

#define NN 100000
#define EMAX 3200000
#define HH 4
#define CC 8
#define HC 32
#define GG 512
#define FIN 128
#define NEG 0.2f

#define SB 1024
#define NBLK ((NN + SB - 1) / SB)   // 98

// ---------------- scratch (static device globals; no allocation) ----------------
__device__ int      d_deg[NN];
__device__ int      d_rowoff[NN + 1];
__device__ int      d_cursor[NN];
__device__ int      d_csrsrc[EMAX];
__device__ int      d_bsum[NBLK];
__device__ int      d_bbase[NBLK];
__device__ __half   d_h16[NN * HC];      // fp16 transformed features, 64B rows
__device__ float    d_als[NN * HH];      // attention logits (src side), float4 rows
__device__ float    d_ald[NN * HH];      // attention logits (dst side), float4 rows
__device__ float    d_xbuf[NN * HC];     // layer activations (elu output), fp32
__device__ unsigned d_asmax[4 * HH];     // per-layer flipped-uint global max of al_s per head
__device__ float    d_gsum[GG * HC];
__device__ float    d_gcnt[GG];
__device__ int      d_is64_edge;
__device__ int      d_is64_batch;

// ---------------- helpers ----------------
__device__ __forceinline__ float lrelu(float x) { return fmaxf(x, NEG * x); }

__device__ __forceinline__ unsigned flipf(float f) {
    unsigned u = __float_as_uint(f);
    return (u & 0x80000000u) ? ~u : (u | 0x80000000u);
}
__device__ __forceinline__ float unflipf(unsigned u) {
    return (u & 0x80000000u) ? __uint_as_float(u ^ 0x80000000u) : __uint_as_float(~u);
}

// ---------------- dtype detection ----------------
__global__ void detect_kernel(const unsigned* __restrict__ e, const unsigned* __restrict__ b) {
    int t = threadIdx.x;                       // 256 threads
    int anyE = 0, anyB = 0;
    for (int k = t; k < 1024; k += 256) anyE |= (e[2 * k + 1] != 0u);
    for (int k = 2000 + t; k < 6000; k += 256) anyB |= (b[2 * k + 1] != 0u);
    __shared__ int sE, sB;
    if (t == 0) { sE = 0; sB = 0; }
    __syncthreads();
    if (anyE) atomicOr(&sE, 1);
    if (anyB) atomicOr(&sB, 1);
    __syncthreads();
    if (t == 0) { d_is64_edge = !sE; d_is64_batch = !sB; }
}

// ---------------- init: zero deg, pool sums, per-layer asmax ----------------
__global__ void init_kernel() {
    int i = blockIdx.x * blockDim.x + threadIdx.x;
    if (i < NN) d_deg[i] = 0;
    if (i < GG * HC) d_gsum[i] = 0.f;
    if (i < GG) d_gcnt[i] = 0.f;
    if (i < 4 * HH) d_asmax[i] = 0u;
}

// ---------------- CSR build ----------------
__global__ void count_kernel(const void* __restrict__ eidx, int E) {
    int e = blockIdx.x * blockDim.x + threadIdx.x;
    if (e >= E) return;
    int dst;
    if (d_is64_edge) dst = (int)((const long long*)eidx)[(size_t)E + e];
    else             dst = ((const int*)eidx)[(size_t)E + e];
    atomicAdd(&d_deg[dst], 1);
}

// phase 1: per-block sums of deg
__global__ void scan_part1() {
    __shared__ int red[32];
    int t = threadIdx.x;
    int i = blockIdx.x * SB + t;
    int v = (i < NN) ? d_deg[i] : 0;
    int s = v;
    s += __shfl_xor_sync(0xffffffffu, s, 1);
    s += __shfl_xor_sync(0xffffffffu, s, 2);
    s += __shfl_xor_sync(0xffffffffu, s, 4);
    s += __shfl_xor_sync(0xffffffffu, s, 8);
    s += __shfl_xor_sync(0xffffffffu, s, 16);
    if ((t & 31) == 0) red[t >> 5] = s;
    __syncthreads();
    if (t < 32) {
        int x = red[t];
        x += __shfl_xor_sync(0xffffffffu, x, 1);
        x += __shfl_xor_sync(0xffffffffu, x, 2);
        x += __shfl_xor_sync(0xffffffffu, x, 4);
        x += __shfl_xor_sync(0xffffffffu, x, 8);
        x += __shfl_xor_sync(0xffffffffu, x, 16);
        if (t == 0) d_bsum[blockIdx.x] = x;
    }
}

// phase 2: scan the 98 block sums
__global__ void scan_part2() {
    __shared__ int sh[128];
    int t = threadIdx.x;                       // 128
    int v = (t < NBLK) ? d_bsum[t] : 0;
    sh[t] = v;
    __syncthreads();
    for (int off = 1; off < 128; off <<= 1) {
        int x = (t >= off) ? sh[t - off] : 0;
        __syncthreads();
        sh[t] += x;
        __syncthreads();
    }
    if (t < NBLK) d_bbase[t] = sh[t] - v;      // exclusive base
    if (t == NBLK - 1) d_rowoff[NN] = sh[t];
}

// phase 3: local exclusive scan + base
__global__ void scan_part3() {
    __shared__ int sh[SB];
    int t = threadIdx.x;
    int i = blockIdx.x * SB + t;
    int v = (i < NN) ? d_deg[i] : 0;
    sh[t] = v;
    __syncthreads();
    for (int off = 1; off < SB; off <<= 1) {
        int x = (t >= off) ? sh[t - off] : 0;
        __syncthreads();
        sh[t] += x;
        __syncthreads();
    }
    int off = d_bbase[blockIdx.x] + sh[t] - v;
    if (i < NN) { d_rowoff[i] = off; d_cursor[i] = off; }
}

__global__ void scatter_kernel(const void* __restrict__ eidx, int E) {
    int e = blockIdx.x * blockDim.x + threadIdx.x;
    if (e >= E) return;
    int s, dst;
    if (d_is64_edge) {
        s   = (int)((const long long*)eidx)[e];
        dst = (int)((const long long*)eidx)[(size_t)E + e];
    } else {
        s   = ((const int*)eidx)[e];
        dst = ((const int*)eidx)[(size_t)E + e];
    }
    int pos = atomicAdd(&d_cursor[dst], 1);
    d_csrsrc[pos] = s;
}

// ---------------- per-layer node transform ----------------

// Layer 1: h = x @ W (128 -> 32), plus attention logits + global max(al_s)
__global__ void k1_first_kernel(const float* __restrict__ x, const float* __restrict__ W,
                                const float* __restrict__ as_, const float* __restrict__ ad_,
                                unsigned* __restrict__ am) {
    __shared__ float sW[FIN * HC];
    __shared__ unsigned smax[HH];
    int t = threadIdx.x;                       // 256
    for (int i = t; i < FIN * HC; i += 256) sW[i] = W[i];
    if (t < HH) smax[t] = 0u;
    __syncthreads();

    int lane = t & 31, w = t >> 5;
    int n = blockIdx.x * 8 + w;                // grid 12500 exact
    float av_s = as_[lane], av_d = ad_[lane];

    float4 xv = ((const float4*)(x + (size_t)n * FIN))[lane];
    float hc = 0.f;
#pragma unroll
    for (int k = 0; k < FIN; k++) {
        float comp = ((k & 3) == 0) ? xv.x : ((k & 3) == 1) ? xv.y : ((k & 3) == 2) ? xv.z : xv.w;
        float xk = __shfl_sync(0xffffffffu, comp, k >> 2);
        hc = fmaf(xk, sW[k * HC + lane], hc);
    }

    float ps = hc * av_s, pd = hc * av_d;
    ps += __shfl_xor_sync(0xffffffffu, ps, 1);
    ps += __shfl_xor_sync(0xffffffffu, ps, 2);
    ps += __shfl_xor_sync(0xffffffffu, ps, 4);
    pd += __shfl_xor_sync(0xffffffffu, pd, 1);
    pd += __shfl_xor_sync(0xffffffffu, pd, 2);
    pd += __shfl_xor_sync(0xffffffffu, pd, 4);

    d_h16[(size_t)n * HC + lane] = __float2half(hc);
    int head = lane >> 3;
    if ((lane & 7) == 0) {
        d_als[n * HH + head] = ps;
        d_ald[n * HH + head] = pd;
        atomicMax(&smax[head], flipf(ps));
    }
    __syncthreads();
    if (t < HH) atomicMax(&am[t], smax[t]);
}

// Layers 2-4: h = xbuf @ W (32 -> 32), same epilogue
__global__ void k1_small_kernel(const float* __restrict__ W,
                                const float* __restrict__ as_, const float* __restrict__ ad_,
                                unsigned* __restrict__ am) {
    __shared__ float sW[HC * HC];
    __shared__ unsigned smax[HH];
    int t = threadIdx.x;                       // 256
    for (int i = t; i < HC * HC; i += 256) sW[i] = W[i];
    if (t < HH) smax[t] = 0u;
    __syncthreads();

    int lane = t & 31, w = t >> 5;
    int n = blockIdx.x * 8 + w;
    float av_s = as_[lane], av_d = ad_[lane];

    float xi = d_xbuf[(size_t)n * HC + lane];
    float hc = 0.f;
#pragma unroll
    for (int k = 0; k < HC; k++) {
        float xk = __shfl_sync(0xffffffffu, xi, k);
        hc = fmaf(xk, sW[k * HC + lane], hc);
    }

    float ps = hc * av_s, pd = hc * av_d;
    ps += __shfl_xor_sync(0xffffffffu, ps, 1);
    ps += __shfl_xor_sync(0xffffffffu, ps, 2);
    ps += __shfl_xor_sync(0xffffffffu, ps, 4);
    pd += __shfl_xor_sync(0xffffffffu, pd, 1);
    pd += __shfl_xor_sync(0xffffffffu, pd, 2);
    pd += __shfl_xor_sync(0xffffffffu, pd, 4);

    d_h16[(size_t)n * HC + lane] = __float2half(hc);
    int head = lane >> 3;
    if ((lane & 7) == 0) {
        d_als[n * HH + head] = ps;
        d_ald[n * HH + head] = pd;
        atomicMax(&smax[head], flipf(ps));
    }
    __syncthreads();
    if (t < HH) atomicMax(&am[t], smax[t]);
}

// ---------------- edge aggregation: one warp per dst node (R6 structure) ----------------
// Softmax via global upper bound m_h = lrelu(max_n al_s[n,h] + al_d[d,h]) (exact).
// q = lane&7 owns channels 4q..4q+3 (head q>>1); g = lane>>3 = edge slot.
// Phase A: lane j owns edge j, computes all 4 head weights -> smem.
// Phase B: one warp-wide LDG.64 gathers the fp16 h-rows of 4 edges at once.
__global__ void edge_kernel(const float* __restrict__ bias, const unsigned* __restrict__ am) {
    __shared__ float4 sw[8][32];               // per-warp edge weights [j] = (w0..w3)
    int t = threadIdx.x, lane = t & 31, w = t >> 5;
    int d = blockIdx.x * 8 + w;                // grid 12500 exact
    int q = lane & 7, g = lane >> 3;
    int head = q >> 1;                         // head of this 4-channel group
    float4* swp = sw[w];
    const uint2* h2 = (const uint2*)d_h16;     // 8B = 4 fp16 channels
    const float4* als4 = (const float4*)d_als;

    float4 aldv = __ldg((const float4*)&d_ald[d * HH]);
    float m0 = lrelu(unflipf(am[0]) + aldv.x);
    float m1 = lrelu(unflipf(am[1]) + aldv.y);
    float m2 = lrelu(unflipf(am[2]) + aldv.z);
    float m3 = lrelu(unflipf(am[3]) + aldv.w);

    // self-loop weight per head
    float4 alsd = __ldg(&als4[d]);
    float s0 = __expf(lrelu(alsd.x + aldv.x) - m0);
    float s1 = __expf(lrelu(alsd.y + aldv.y) - m1);
    float s2 = __expf(lrelu(alsd.z + aldv.z) - m2);
    float s3 = __expf(lrelu(alsd.w + aldv.w) - m3);
    float wselfq = (head == 0) ? s0 : (head == 1) ? s1 : (head == 2) ? s2 : s3;

    float4 acc = make_float4(0.f, 0.f, 0.f, 0.f);
    if (g == 0) {
        uint2 hv = __ldg(&h2[(size_t)d * 8 + q]);
        float2 f0 = __half22float2(*(const __half2*)&hv.x);
        float2 f1 = __half22float2(*(const __half2*)&hv.y);
        acc.x = wselfq * f0.x; acc.y = wselfq * f0.y;
        acc.z = wselfq * f1.x; acc.w = wselfq * f1.y;
    }
    float dn0 = 0.f, dn1 = 0.f, dn2 = 0.f, dn3 = 0.f;

    int beg = d_rowoff[d], end = d_rowoff[d + 1];
    for (int base = beg; base < end; base += 32) {
        // phase A: lane j owns edge j — compute all 4 head weights
        int idx = base + lane;
        bool v = idx < end;
        int s = v ? __ldg(&d_csrsrc[idx]) : 0;
        float4 a = __ldg(&als4[s]);
        float w0 = __expf(lrelu(a.x + aldv.x) - m0);
        float w1 = __expf(lrelu(a.y + aldv.y) - m1);
        float w2 = __expf(lrelu(a.z + aldv.z) - m2);
        float w3 = __expf(lrelu(a.w + aldv.w) - m3);
        if (!v) { w0 = w1 = w2 = w3 = 0.f; }
        dn0 += w0; dn1 += w1; dn2 += w2; dn3 += w3;
        swp[lane] = make_float4(w0, w1, w2, w3);
        __syncwarp();

        // phase B: 4 edges per iteration; lane handles 4-channel group q of edge sub*4+g
#pragma unroll
        for (int sub = 0; sub < 8; sub++) {
            int j = sub * 4 + g;
            int sj = __shfl_sync(0xffffffffu, s, j);
            uint2 hv = __ldg(&h2[(size_t)sj * 8 + q]);
            float wj = ((const float*)swp)[j * 4 + head];
            float2 f0 = __half22float2(*(const __half2*)&hv.x);
            float2 f1 = __half22float2(*(const __half2*)&hv.y);
            acc.x = fmaf(wj, f0.x, acc.x);
            acc.y = fmaf(wj, f0.y, acc.y);
            acc.z = fmaf(wj, f1.x, acc.z);
            acc.w = fmaf(wj, f1.y, acc.w);
        }
        __syncwarp();
    }

    // reduce accumulators across the 4 edge-slot groups (same q)
    acc.x += __shfl_xor_sync(0xffffffffu, acc.x, 8);
    acc.y += __shfl_xor_sync(0xffffffffu, acc.y, 8);
    acc.z += __shfl_xor_sync(0xffffffffu, acc.z, 8);
    acc.w += __shfl_xor_sync(0xffffffffu, acc.w, 8);
    acc.x += __shfl_xor_sync(0xffffffffu, acc.x, 16);
    acc.y += __shfl_xor_sync(0xffffffffu, acc.y, 16);
    acc.z += __shfl_xor_sync(0xffffffffu, acc.z, 16);
    acc.w += __shfl_xor_sync(0xffffffffu, acc.w, 16);

    // reduce per-head denominators across all lanes
#pragma unroll
    for (int off = 1; off < 32; off <<= 1) {
        dn0 += __shfl_xor_sync(0xffffffffu, dn0, off);
        dn1 += __shfl_xor_sync(0xffffffffu, dn1, off);
        dn2 += __shfl_xor_sync(0xffffffffu, dn2, off);
        dn3 += __shfl_xor_sync(0xffffffffu, dn3, off);
    }

    if (lane < 8) {
        float dh = (head == 0) ? dn0 : (head == 1) ? dn1 : (head == 2) ? dn2 : dn3;
        float inv = 1.0f / (wselfq + dh);
        float4 bq = __ldg(&((const float4*)bias)[q]);
        float4 o;
        o.x = acc.x * inv + bq.x;
        o.y = acc.y * inv + bq.y;
        o.z = acc.z * inv + bq.z;
        o.w = acc.w * inv + bq.w;
        o.x = (o.x > 0.f) ? o.x : (__expf(o.x) - 1.f);
        o.y = (o.y > 0.f) ? o.y : (__expf(o.y) - 1.f);
        o.z = (o.z > 0.f) ? o.z : (__expf(o.z) - 1.f);
        o.w = (o.w > 0.f) ? o.w : (__expf(o.w) - 1.f);
        ((float4*)d_xbuf)[(size_t)d * 8 + q] = o;
    }
}

// ---------------- pooling (exploits sorted batch: register-accumulate, flush on change) ----------------
__global__ void pool_kernel(const void* __restrict__ batch) {
    int t = threadIdx.x, lane = t & 31, w = t >> 5;
    int base = (blockIdx.x * 8 + w) * 32;      // this warp's 32 consecutive nodes
    if (base >= NN) return;
    int endn = base + 32; if (endn > NN) endn = NN;

    float acc = 0.f, cnt = 0.f;
    int gcur = -1;
    for (int n = base; n < endn; n++) {
        int g;
        if (d_is64_batch) g = (int)((const long long*)batch)[n];
        else              g = ((const int*)batch)[n];
        if (g != gcur) {
            if (gcur >= 0) {
                atomicAdd(&d_gsum[gcur * HC + lane], acc);
                if (lane == 0) atomicAdd(&d_gcnt[gcur], cnt);
            }
            gcur = g; acc = 0.f; cnt = 0.f;
        }
        acc += d_xbuf[(size_t)n * HC + lane];
        cnt += 1.f;
    }
    if (gcur >= 0) {
        atomicAdd(&d_gsum[gcur * HC + lane], acc);
        if (lane == 0) atomicAdd(&d_gcnt[gcur], cnt);
    }
}

__global__ void final_kernel(const float* __restrict__ fc_w, const float* __restrict__ fc_b,
                             float* __restrict__ out) {
    int g = blockIdx.x * blockDim.x + threadIdx.x;
    if (g >= GG) return;
    float inv = 1.0f / fmaxf(d_gcnt[g], 1.0f);
    float s = 0.f;
#pragma unroll
    for (int c = 0; c < HC; c++) s = fmaf(d_gsum[g * HC + c] * inv, fc_w[c], s);
    out[g] = s + fc_b[0];
}

// ---------------- launch ----------------
extern "C" void kernel_launch(void* const* d_in, const int* in_sizes, int n_in,
                              void* d_out, int out_size) {
    const float* x     = (const float*)d_in[0];
    const void*  eidx  = d_in[1];
    const void*  batch = d_in[2];
    const float* W1  = (const float*)d_in[3];
    const float* as1 = (const float*)d_in[4];
    const float* ad1 = (const float*)d_in[5];
    const float* b1  = (const float*)d_in[6];
    const float* fc_w = (const float*)d_in[19];
    const float* fc_b = (const float*)d_in[20];
    float* out = (float*)d_out;

    int E = in_sizes[1] / 2;
    if (E > EMAX) E = EMAX;
    if (E < 0) E = 0;

    const int NB = NN / 8;                 // 12500 blocks of 8 warps
    const int EB = (E + 255) / 256;

    // resolve device-global addresses for per-layer asmax slots
    unsigned* am_base = nullptr;
    cudaGetSymbolAddress((void**)&am_base, d_asmax);

    detect_kernel<<<1, 256>>>((const unsigned*)eidx, (const unsigned*)batch);
    init_kernel<<<(NN + 255) / 256, 256>>>();

    // CSR build (parallel 3-phase scan)
    if (EB > 0) count_kernel<<<EB, 256>>>(eidx, E);
    scan_part1<<<NBLK, SB>>>();
    scan_part2<<<1, 128>>>();
    scan_part3<<<NBLK, SB>>>();
    if (EB > 0) scatter_kernel<<<EB, 256>>>(eidx, E);

    // Layer 1 (input dim 128)
    k1_first_kernel<<<NB, 256>>>(x, W1, as1, ad1, am_base + 0 * HH);
    edge_kernel<<<NB, 256>>>(b1, am_base + 0 * HH);

    // Layers 2-4 (input dim 32)
    for (int L = 1; L < 4; L++) {
        const float* W   = (const float*)d_in[3 + 4 * L];
        const float* as_ = (const float*)d_in[4 + 4 * L];
        const float* ad_ = (const float*)d_in[5 + 4 * L];
        const float* b_  = (const float*)d_in[6 + 4 * L];
        k1_small_kernel<<<NB, 256>>>(W, as_, ad_, am_base + L * HH);
        edge_kernel<<<NB, 256>>>(b_, am_base + L * HH);
    }

    // Global mean pool + FC
    pool_kernel<<<(NN + 255) / 256, 256>>>(batch);
    final_kernel<<<2, 256>>>(fc_w, fc_b, out);
}